// round 1
// baseline (speedup 1.0000x reference)
#include <cuda_runtime.h>
#include <math.h>

#define B_    256
#define D_    2048
#define NM    16384      // C_CAM * P
#define P_    2048
#define CCAM  8
#define KTOP  50
#define TINV  (1.0f/0.07f)

// scratch (static device globals — no allocation allowed)
__device__ float g_xn[B_ * D_];        // normalized inputs, 2 MB
__device__ float g_logits[B_ * NM];    // all_logits, 16 MB (fits L2)
__device__ float g_ce[B_];
__device__ float g_lossk[B_];

// ---------------------------------------------------------------------------
// Kernel 1: L2-normalize each input row
// ---------------------------------------------------------------------------
__global__ void __launch_bounds__(256) knorm(const float* __restrict__ x) {
    __shared__ float red[8];
    int b = blockIdx.x;
    int t = threadIdx.x;
    const float* row = x + (size_t)b * D_;
    float s = 0.f;
    for (int i = t; i < D_; i += 256) { float v = row[i]; s += v * v; }
    #pragma unroll
    for (int o = 16; o > 0; o >>= 1) s += __shfl_down_sync(0xffffffffu, s, o);
    if ((t & 31) == 0) red[t >> 5] = s;
    __syncthreads();
    if (t < 8) {
        float w = red[t];
        #pragma unroll
        for (int o = 4; o > 0; o >>= 1) w += __shfl_down_sync(0xffu, w, o);
        if (t == 0) red[0] = w;
    }
    __syncthreads();
    float inv = rsqrtf(red[0]);
    for (int i = t; i < D_; i += 256) g_xn[(size_t)b * D_ + i] = row[i] * inv;
}

// ---------------------------------------------------------------------------
// Kernel 2: SGEMM  C[M,N] = A[M,K] * B[N,K]^T   (A = g_xn, B = tempV)
// 128x128 tile, BK=8, 8x8 thread tile, 256 threads
// ---------------------------------------------------------------------------
#define BM 128
#define BN 128
#define BK 8
__global__ void __launch_bounds__(256) kgemm(const float* __restrict__ Bmat) {
    __shared__ float As[BK][BM];
    __shared__ float Bs[BK][BN];
    int t = threadIdx.x;
    int mBase = blockIdx.y * BM;
    int nBase = blockIdx.x * BN;

    int lr = t >> 1;           // 0..127 : tile row for loading
    int lc = (t & 1) * 4;      // 0 or 4 : k-offset (float4)
    int tr = (t >> 4) * 8;     // output row group
    int tc = (t & 15) * 8;     // output col group

    float acc[8][8];
    #pragma unroll
    for (int i = 0; i < 8; i++)
        #pragma unroll
        for (int j = 0; j < 8; j++) acc[i][j] = 0.f;

    const float* Aptr = g_xn + (size_t)(mBase + lr) * D_ + lc;
    const float* Bptr = Bmat + (size_t)(nBase + lr) * D_ + lc;

    for (int k0 = 0; k0 < D_; k0 += BK) {
        float4 a4 = *(const float4*)(Aptr + k0);
        float4 b4 = *(const float4*)(Bptr + k0);
        As[lc + 0][lr] = a4.x; As[lc + 1][lr] = a4.y;
        As[lc + 2][lr] = a4.z; As[lc + 3][lr] = a4.w;
        Bs[lc + 0][lr] = b4.x; Bs[lc + 1][lr] = b4.y;
        Bs[lc + 2][lr] = b4.z; Bs[lc + 3][lr] = b4.w;
        __syncthreads();
        #pragma unroll
        for (int k = 0; k < BK; k++) {
            float ar[8], br[8];
            *(float4*)&ar[0] = *(const float4*)&As[k][tr];
            *(float4*)&ar[4] = *(const float4*)&As[k][tr + 4];
            *(float4*)&br[0] = *(const float4*)&Bs[k][tc];
            *(float4*)&br[4] = *(const float4*)&Bs[k][tc + 4];
            #pragma unroll
            for (int i = 0; i < 8; i++)
                #pragma unroll
                for (int j = 0; j < 8; j++)
                    acc[i][j] += ar[i] * br[j];
        }
        __syncthreads();
    }
    #pragma unroll
    for (int i = 0; i < 8; i++) {
        float* c = g_logits + (size_t)(mBase + tr + i) * NM + nBase + tc;
        *(float4*)c       = make_float4(acc[i][0], acc[i][1], acc[i][2], acc[i][3]);
        *((float4*)c + 1) = make_float4(acc[i][4], acc[i][5], acc[i][6], acc[i][7]);
    }
}

// ---------------------------------------------------------------------------
// Kernel 3: per-sample reductions (one CTA per sample)
// ---------------------------------------------------------------------------
__device__ __forceinline__ float blockMaxF(float v, float* scratch) {
    int t = threadIdx.x;
    #pragma unroll
    for (int o = 16; o > 0; o >>= 1) v = fmaxf(v, __shfl_down_sync(0xffffffffu, v, o));
    if ((t & 31) == 0) scratch[t >> 5] = v;
    __syncthreads();
    if (t < 8) {
        float w = scratch[t];
        #pragma unroll
        for (int o = 4; o > 0; o >>= 1) w = fmaxf(w, __shfl_down_sync(0xffu, w, o));
        if (t == 0) scratch[0] = w;
    }
    __syncthreads();
    float r = scratch[0];
    __syncthreads();
    return r;
}
__device__ __forceinline__ float blockSumF(float v, float* scratch) {
    int t = threadIdx.x;
    #pragma unroll
    for (int o = 16; o > 0; o >>= 1) v += __shfl_down_sync(0xffffffffu, v, o);
    if ((t & 31) == 0) scratch[t >> 5] = v;
    __syncthreads();
    if (t < 8) {
        float w = scratch[t];
        #pragma unroll
        for (int o = 4; o > 0; o >>= 1) w += __shfl_down_sync(0xffu, w, o);
        if (t == 0) scratch[0] = w;
    }
    __syncthreads();
    float r = scratch[0];
    __syncthreads();
    return r;
}

__global__ void __launch_bounds__(256) krow(const int* __restrict__ labels,
                                            const int* __restrict__ cams) {
    extern __shared__ float sv[];                 // NM floats (64 KB)
    __shared__ float fred[8];
    __shared__ unsigned long long ured[8];
    __shared__ unsigned long long winner;

    int b = blockIdx.x;
    int t = threadIdx.x;
    const float* row = g_logits + (size_t)b * NM;
    for (int i = t; i < NM; i += 256) sv[i] = row[i];
    __syncthreads();

    int cam = cams[b];
    int lab = labels[b];

    // ---- intra-camera CE (uses unmasked values) ----
    int base = cam * P_;
    float mx = -INFINITY;
    for (int i = t; i < P_; i += 256) mx = fmaxf(mx, sv[base + i]);
    float mxall = blockMaxF(mx, fred);
    float s = 0.f;
    for (int i = t; i < P_; i += 256) s += expf((sv[base + i] - mxall) * TINV);
    float sall = blockSumF(s, fred);
    if (t == 0) {
        float lse = mxall * TINV + logf(sall);
        g_ce[b] = lse - sv[base + lab] * TINV;
    }
    __syncthreads();

    // ---- inter-camera: read positives, then mask them ----
    float ori[CCAM];   // meaningful on thread 0 only
    float maxori = -INFINITY;
    if (t == 0) {
        #pragma unroll
        for (int c = 0; c < CCAM; c++) {
            ori[c] = sv[lab + P_ * c];
            maxori = fmaxf(maxori, ori[c]);
        }
        #pragma unroll
        for (int c = 0; c < CCAM; c++) sv[lab + P_ * c] = -10000.0f;
    }
    __syncthreads();

    // ---- top-K selection: 50 iterative masked argmax passes ----
    float m = 0.f, ssum = 0.f;    // thread 0 state
    for (int it = 0; it < KTOP; ++it) {
        unsigned long long best = 0ull;
        for (int i = t; i < NM; i += 256) {
            unsigned u = __float_as_uint(sv[i]);
            u = (u & 0x80000000u) ? ~u : (u | 0x80000000u);   // order-preserving
            unsigned long long p = ((unsigned long long)u << 32) | (unsigned)i;
            if (p > best) best = p;
        }
        #pragma unroll
        for (int o = 16; o > 0; o >>= 1) {
            unsigned long long q = __shfl_down_sync(0xffffffffu, best, o);
            if (q > best) best = q;
        }
        if ((t & 31) == 0) ured[t >> 5] = best;
        __syncthreads();
        if (t < 8) {
            unsigned long long w = ured[t];
            #pragma unroll
            for (int o = 4; o > 0; o >>= 1) {
                unsigned long long q = __shfl_down_sync(0xffu, w, o);
                if (q > w) w = q;
            }
            if (t == 0) winner = w;
        }
        __syncthreads();
        if (t == 0) {
            int idx = (int)(winner & 0xffffffffu);
            float v = sv[idx];
            if (it == 0) {
                m = fmaxf(v, maxori);
                ssum = 0.f;
                #pragma unroll
                for (int c = 0; c < CCAM; c++) ssum += expf((ori[c] - m) * TINV);
            }
            ssum += expf((v - m) * TINV);
            sv[idx] = -INFINITY;   // mask for next pass
        }
        __syncthreads();
    }
    if (t == 0) {
        float lse = m * TINV + logf(ssum);
        float mean = 0.f;
        #pragma unroll
        for (int c = 0; c < CCAM; c++) mean += ori[c];
        mean = mean * TINV / (float)CCAM;
        g_lossk[b] = lse - mean;
    }
}

// ---------------------------------------------------------------------------
// Kernel 4: deterministic per-camera segment means -> 2 scalars
// ---------------------------------------------------------------------------
__global__ void kfinal(const int* __restrict__ cams, float* __restrict__ out) {
    __shared__ float mce[CCAM], mlk[CCAM];
    int t = threadIdx.x;
    if (t < CCAM) {
        float sc = 0.f, sl = 0.f; int cnt = 0;
        for (int i = 0; i < B_; i++) {
            if (cams[i] == t) { sc += g_ce[i]; sl += g_lossk[i]; cnt++; }
        }
        mce[t] = (cnt > 0) ? sc / (float)cnt : 0.f;
        mlk[t] = (cnt > 0) ? sl / (float)cnt : 0.f;
    }
    __syncthreads();
    if (t == 0) {
        float li = 0.f, lk = 0.f;
        #pragma unroll
        for (int c = 0; c < CCAM; c++) { li += mce[c]; lk += mlk[c]; }
        out[0] = li;
        out[1] = 0.5f * lk;   // LOSS_WEIGHT
    }
}

// ---------------------------------------------------------------------------
extern "C" void kernel_launch(void* const* d_in, const int* in_sizes, int n_in,
                              void* d_out, int out_size) {
    const float* x      = (const float*)d_in[0];
    const int*   labels = (const int*)d_in[1];
    const int*   cams   = (const int*)d_in[2];
    const float* tempV  = (const float*)d_in[3];
    float* out = (float*)d_out;

    knorm<<<B_, 256>>>(x);

    dim3 g(NM / BN, B_ / BM);
    kgemm<<<g, 256>>>(tempV);

    cudaFuncSetAttribute(krow, cudaFuncAttributeMaxDynamicSharedMemorySize,
                         NM * (int)sizeof(float) + 1024);
    krow<<<B_, 256, NM * sizeof(float)>>>(labels, cams);

    kfinal<<<1, 32>>>(cams, out);
}

// round 3
// speedup vs baseline: 2.8730x; 2.8730x over previous
#include <cuda_runtime.h>
#include <math.h>
#include <stdint.h>

#define B_    256
#define D_    2048
#define NM    16384      // C_CAM * P
#define P_    2048
#define CCAM  8
#define KTOP  50
#define TINV  (1.0f/0.07f)

// scratch (static device globals — no allocation allowed)
__device__ float g_xn[B_ * D_];        // normalized inputs, 2 MB
__device__ float g_logits[B_ * NM];    // all_logits, 16 MB (L2-resident)
__device__ float g_ce[B_];
__device__ float g_lossk[B_];

// ---------------------------------------------------------------------------
__device__ __forceinline__ uint32_t smem_u32(const void* p) {
    uint32_t a;
    asm("{ .reg .u64 t; cvta.to.shared.u64 t, %1; cvt.u32.u64 %0, t; }"
        : "=r"(a) : "l"(p));
    return a;
}
__device__ __forceinline__ void cpa16(uint32_t s, const void* g) {
    asm volatile("cp.async.cg.shared.global [%0], [%1], 16;" :: "r"(s), "l"(g) : "memory");
}

// ---------------------------------------------------------------------------
// Kernel 1: L2-normalize each input row
// ---------------------------------------------------------------------------
__global__ void __launch_bounds__(256) knorm(const float* __restrict__ x) {
    __shared__ float red[8];
    int b = blockIdx.x;
    int t = threadIdx.x;
    const float* row = x + (size_t)b * D_;
    float s = 0.f;
    for (int i = t; i < D_; i += 256) { float v = row[i]; s += v * v; }
    #pragma unroll
    for (int o = 16; o > 0; o >>= 1) s += __shfl_down_sync(0xffffffffu, s, o);
    if ((t & 31) == 0) red[t >> 5] = s;
    __syncthreads();
    if (t < 8) {
        float w = red[t];
        #pragma unroll
        for (int o = 4; o > 0; o >>= 1) w += __shfl_down_sync(0xffu, w, o);
        if (t == 0) red[0] = w;
    }
    __syncthreads();
    float inv = rsqrtf(red[0]);
    for (int i = t; i < D_; i += 256) g_xn[(size_t)b * D_ + i] = row[i] * inv;
}

// ---------------------------------------------------------------------------
// Kernel 2: tf32 mma.sync GEMM  C[256,16384] = g_xn @ tempV^T
// CTA 128x128, BK=32, 8 warps (warp tile 64x32), cp.async double buffer.
// SMEM row stride = 36 floats (stride%32==4 -> conflict-free fragment LDS).
// ---------------------------------------------------------------------------
#define BM 128
#define BN 128
#define BK 32
#define NCH (D_ / BK)            // 64
#define ROWSTR 36                // floats per SMEM row (32 data + 4 pad)
#define ATILE_F (BM * ROWSTR)    // 4608 floats = 18432 B
#define STAGE_F (2 * ATILE_F)    // A + B per stage (9216 floats = 36864 B)
#define GEMM_SMEM (2 * STAGE_F * 4)  // 73728 B

__global__ void __launch_bounds__(256, 2) kgemm(const float* __restrict__ Bmat) {
    extern __shared__ float sm[];
    uint32_t sbase = smem_u32(sm);
    int t = threadIdx.x, lane = t & 31, wid = t >> 5;
    int warp_m = (wid & 1) * 64, warp_n = (wid >> 1) * 32;
    int gid = lane >> 2, tig = lane & 3;
    int mBase = blockIdx.y * BM, nBase = blockIdx.x * BN;

    float acc[4][4][4];
    #pragma unroll
    for (int i = 0; i < 4; i++)
        #pragma unroll
        for (int j = 0; j < 4; j++)
            #pragma unroll
            for (int q = 0; q < 4; q++) acc[i][j][q] = 0.f;

    auto loadc = [&](int stage, int c) {
        int k0 = c * BK;
        uint32_t As = sbase + stage * (STAGE_F * 4);
        uint32_t Bs = As + ATILE_F * 4;
        #pragma unroll
        for (int r = 0; r < 4; r++) {
            int i = t + r * 256, row = i >> 3, q = i & 7;
            cpa16(As + (uint32_t)(row * ROWSTR + q * 4) * 4,
                  g_xn + (size_t)(mBase + row) * D_ + k0 + q * 4);
        }
        #pragma unroll
        for (int r = 0; r < 4; r++) {
            int i = t + r * 256, row = i >> 3, q = i & 7;
            cpa16(Bs + (uint32_t)(row * ROWSTR + q * 4) * 4,
                  Bmat + (size_t)(nBase + row) * D_ + k0 + q * 4);
        }
    };

    loadc(0, 0); asm volatile("cp.async.commit_group;" ::: "memory");
    loadc(1, 1); asm volatile("cp.async.commit_group;" ::: "memory");

    for (int c = 0; c < NCH; c++) {
        asm volatile("cp.async.wait_group 1;" ::: "memory");
        __syncthreads();
        const float* As = sm + (c & 1) * STAGE_F;
        const float* Bs = As + ATILE_F;
        #pragma unroll
        for (int kk = 0; kk < 4; kk++) {
            uint32_t a[4][4], b[4][2];
            #pragma unroll
            for (int mt = 0; mt < 4; mt++) {
                const float* p = As + (warp_m + mt * 16 + gid) * ROWSTR + kk * 8 + tig;
                a[mt][0] = __float_as_uint(p[0]);
                a[mt][1] = __float_as_uint(p[8 * ROWSTR]);
                a[mt][2] = __float_as_uint(p[4]);
                a[mt][3] = __float_as_uint(p[8 * ROWSTR + 4]);
            }
            #pragma unroll
            for (int nt = 0; nt < 4; nt++) {
                const float* p = Bs + (warp_n + nt * 8 + gid) * ROWSTR + kk * 8 + tig;
                b[nt][0] = __float_as_uint(p[0]);
                b[nt][1] = __float_as_uint(p[4]);
            }
            #pragma unroll
            for (int mt = 0; mt < 4; mt++)
                #pragma unroll
                for (int nt = 0; nt < 4; nt++)
                    asm volatile(
                        "mma.sync.aligned.m16n8k8.row.col.f32.tf32.tf32.f32 "
                        "{%0,%1,%2,%3},{%4,%5,%6,%7},{%8,%9},{%0,%1,%2,%3};"
                        : "+f"(acc[mt][nt][0]), "+f"(acc[mt][nt][1]),
                          "+f"(acc[mt][nt][2]), "+f"(acc[mt][nt][3])
                        : "r"(a[mt][0]), "r"(a[mt][1]), "r"(a[mt][2]), "r"(a[mt][3]),
                          "r"(b[nt][0]), "r"(b[nt][1]));
        }
        __syncthreads();
        if (c + 2 < NCH) loadc(c & 1, c + 2);
        asm volatile("cp.async.commit_group;" ::: "memory");
    }

    // epilogue: direct fp32 stores (float2 per c-pair)
    #pragma unroll
    for (int mt = 0; mt < 4; mt++) {
        int row0 = mBase + warp_m + mt * 16 + gid;
        #pragma unroll
        for (int nt = 0; nt < 4; nt++) {
            int col = nBase + warp_n + nt * 8 + 2 * tig;
            *(float2*)(g_logits + (size_t)row0 * NM + col) =
                make_float2(acc[mt][nt][0], acc[mt][nt][1]);
            *(float2*)(g_logits + (size_t)(row0 + 8) * NM + col) =
                make_float2(acc[mt][nt][2], acc[mt][nt][3]);
        }
    }
}

// ---------------------------------------------------------------------------
// Kernel 3: per-sample reductions, incremental top-K
// ---------------------------------------------------------------------------
__device__ __forceinline__ float blockMaxF(float v, float* scratch) {
    int t = threadIdx.x;
    #pragma unroll
    for (int o = 16; o > 0; o >>= 1) v = fmaxf(v, __shfl_down_sync(0xffffffffu, v, o));
    if ((t & 31) == 0) scratch[t >> 5] = v;
    __syncthreads();
    if (t < 8) {
        float w = scratch[t];
        #pragma unroll
        for (int o = 4; o > 0; o >>= 1) w = fmaxf(w, __shfl_down_sync(0xffu, w, o));
        if (t == 0) scratch[0] = w;
    }
    __syncthreads();
    float r = scratch[0];
    __syncthreads();
    return r;
}
__device__ __forceinline__ float blockSumF(float v, float* scratch) {
    int t = threadIdx.x;
    #pragma unroll
    for (int o = 16; o > 0; o >>= 1) v += __shfl_down_sync(0xffffffffu, v, o);
    if ((t & 31) == 0) scratch[t >> 5] = v;
    __syncthreads();
    if (t < 8) {
        float w = scratch[t];
        #pragma unroll
        for (int o = 4; o > 0; o >>= 1) w += __shfl_down_sync(0xffu, w, o);
        if (t == 0) scratch[0] = w;
    }
    __syncthreads();
    float r = scratch[0];
    __syncthreads();
    return r;
}
__device__ __forceinline__ unsigned long long packVI(float f, int idx) {
    unsigned u = __float_as_uint(f);
    u = (u & 0x80000000u) ? ~u : (u | 0x80000000u);     // order-preserving
    return ((unsigned long long)u << 32) | (unsigned)idx;
}

__global__ void __launch_bounds__(256) krow(const int* __restrict__ labels,
                                            const int* __restrict__ cams) {
    extern __shared__ float sv[];                 // NM floats (64 KB)
    __shared__ unsigned long long arr[256];
    __shared__ float fred[8];
    __shared__ unsigned long long wred[8];
    __shared__ unsigned long long s_win;
    __shared__ float s_ori[CCAM];

    int b = blockIdx.x;
    int t = threadIdx.x;
    const float* row = g_logits + (size_t)b * NM;
    for (int i = t; i < NM; i += 256) sv[i] = row[i];
    __syncthreads();

    int cam = cams[b];
    int lab = labels[b];

    // ---- intra-camera CE (unmasked values) ----
    int base = cam * P_;
    float mx = -INFINITY;
    for (int i = t; i < P_; i += 256) mx = fmaxf(mx, sv[base + i]);
    float mxall = blockMaxF(mx, fred);
    float s = 0.f;
    for (int i = t; i < P_; i += 256) s += expf((sv[base + i] - mxall) * TINV);
    float sall = blockSumF(s, fred);
    if (t == 0) {
        float lse = mxall * TINV + logf(sall);
        g_ce[b] = lse - sv[base + lab] * TINV;
    }
    __syncthreads();

    // ---- inter-camera: capture positives, then mask them ----
    float maxori = -INFINITY;
    if (t == 0) {
        #pragma unroll
        for (int c = 0; c < CCAM; c++) {
            s_ori[c] = sv[lab + P_ * c];
            maxori = fmaxf(maxori, s_ori[c]);
        }
        #pragma unroll
        for (int c = 0; c < CCAM; c++) sv[lab + P_ * c] = -10000.0f;
    }
    __syncthreads();

    // ---- initial per-thread max over strided slice ----
    unsigned long long best = 0ull;
    #pragma unroll 8
    for (int j = 0; j < NM / 256; j++) {
        int i = t + 256 * j;
        unsigned long long p = packVI(sv[i], i);
        if (p > best) best = p;
    }
    arr[t] = best;
    __syncthreads();

    // ---- 50 incremental argmax passes ----
    float m = 0.f, ssum = 0.f;    // thread 0 state
    for (int it = 0; it < KTOP; ++it) {
        unsigned long long v = arr[t];
        #pragma unroll
        for (int o = 16; o > 0; o >>= 1) {
            unsigned long long q = __shfl_down_sync(0xffffffffu, v, o);
            if (q > v) v = q;
        }
        if ((t & 31) == 0) wred[t >> 5] = v;
        __syncthreads();
        if (t < 8) {
            unsigned long long w = wred[t];
            #pragma unroll
            for (int o = 4; o > 0; o >>= 1) {
                unsigned long long q = __shfl_down_sync(0xffu, w, o);
                if (q > w) w = q;
            }
            if (t == 0) s_win = w;
        }
        __syncthreads();
        unsigned long long win = s_win;
        int idx = (int)(win & 0xffffffffu);
        if (t == 0) {
            unsigned u = (unsigned)(win >> 32);
            float val = (u & 0x80000000u) ? __uint_as_float(u ^ 0x80000000u)
                                          : __uint_as_float(~u);
            if (it == 0) {
                m = fmaxf(val, maxori);
                ssum = 0.f;
                #pragma unroll
                for (int c = 0; c < CCAM; c++) ssum += expf((s_ori[c] - m) * TINV);
            }
            ssum += expf((val - m) * TINV);
        }
        if (t == (idx & 255)) {           // owner rescans its 64-elem slice
            sv[idx] = -INFINITY;
            unsigned long long nb = 0ull;
            #pragma unroll 8
            for (int j = 0; j < NM / 256; j++) {
                int i = t + 256 * j;
                unsigned long long p = packVI(sv[i], i);
                if (p > nb) nb = p;
            }
            arr[t] = nb;
        }
        __syncthreads();
    }
    if (t == 0) {
        float lse = m * TINV + logf(ssum);
        float mean = 0.f;
        #pragma unroll
        for (int c = 0; c < CCAM; c++) mean += s_ori[c];
        mean = mean * TINV / (float)CCAM;
        g_lossk[b] = lse - mean;
    }
}

// ---------------------------------------------------------------------------
// Kernel 4: deterministic per-camera segment means -> 2 scalars
// ---------------------------------------------------------------------------
__global__ void __launch_bounds__(256) kfinal(const int* __restrict__ cams,
                                              float* __restrict__ out) {
    __shared__ int sc_cam[B_];
    __shared__ float sce[B_], slk[B_];
    __shared__ float mce[CCAM], mlk[CCAM];
    int t = threadIdx.x;
    sc_cam[t] = cams[t];
    sce[t] = g_ce[t];
    slk[t] = g_lossk[t];
    __syncthreads();
    if (t < CCAM) {
        float sc = 0.f, sl = 0.f; int cnt = 0;
        for (int i = 0; i < B_; i++) {
            if (sc_cam[i] == t) { sc += sce[i]; sl += slk[i]; cnt++; }
        }
        mce[t] = (cnt > 0) ? sc / (float)cnt : 0.f;
        mlk[t] = (cnt > 0) ? sl / (float)cnt : 0.f;
    }
    __syncthreads();
    if (t == 0) {
        float li = 0.f, lk = 0.f;
        #pragma unroll
        for (int c = 0; c < CCAM; c++) { li += mce[c]; lk += mlk[c]; }
        out[0] = li;
        out[1] = 0.5f * lk;   // LOSS_WEIGHT
    }
}

// ---------------------------------------------------------------------------
extern "C" void kernel_launch(void* const* d_in, const int* in_sizes, int n_in,
                              void* d_out, int out_size) {
    const float* x      = (const float*)d_in[0];
    const int*   labels = (const int*)d_in[1];
    const int*   cams   = (const int*)d_in[2];
    const float* tempV  = (const float*)d_in[3];
    float* out = (float*)d_out;

    knorm<<<B_, 256>>>(x);

    cudaFuncSetAttribute(kgemm, cudaFuncAttributeMaxDynamicSharedMemorySize,
                         GEMM_SMEM);
    dim3 g(NM / BN, B_ / BM);          // 128 x 2 = 256 CTAs
    kgemm<<<g, 256, GEMM_SMEM>>>(tempV);

    cudaFuncSetAttribute(krow, cudaFuncAttributeMaxDynamicSharedMemorySize,
                         NM * (int)sizeof(float) + 1024);
    krow<<<B_, 256, NM * sizeof(float)>>>(labels, cams);

    kfinal<<<1, 256>>>(cams, out);
}

// round 4
// speedup vs baseline: 3.5029x; 1.2192x over previous
#include <cuda_runtime.h>
#include <math.h>
#include <stdint.h>

#define B_    256
#define D_    2048
#define NM    16384      // C_CAM * P
#define P_    2048
#define CCAM  8
#define KTOP  50
#define TINV  (1.0f/0.07f)

// scratch (static device globals — no allocation allowed)
__device__ float g_xn[B_ * D_];        // normalized inputs, 2 MB
__device__ float g_logits[B_ * NM];    // all_logits, 16 MB (L2-resident)
__device__ float g_ce[B_];
__device__ float g_lossk[B_];

// ---------------------------------------------------------------------------
__device__ __forceinline__ uint32_t smem_u32(const void* p) {
    uint32_t a;
    asm("{ .reg .u64 t; cvta.to.shared.u64 t, %1; cvt.u32.u64 %0, t; }"
        : "=r"(a) : "l"(p));
    return a;
}
__device__ __forceinline__ void cpa16(uint32_t s, const void* g) {
    asm volatile("cp.async.cg.shared.global [%0], [%1], 16;" :: "r"(s), "l"(g) : "memory");
}
// pack two fp32 -> f16x2 (lo = first element / lower k)
__device__ __forceinline__ uint32_t packh(float2 v) {
    uint32_t r;
    asm("cvt.rn.f16x2.f32 %0, %1, %2;" : "=r"(r) : "f"(v.y), "f"(v.x));
    return r;
}

// ---------------------------------------------------------------------------
// Kernel 1: L2-normalize each input row
// ---------------------------------------------------------------------------
__global__ void __launch_bounds__(256) knorm(const float* __restrict__ x) {
    __shared__ float red[8];
    int b = blockIdx.x;
    int t = threadIdx.x;
    const float* row = x + (size_t)b * D_;
    float s = 0.f;
    for (int i = t; i < D_; i += 256) { float v = row[i]; s += v * v; }
    #pragma unroll
    for (int o = 16; o > 0; o >>= 1) s += __shfl_down_sync(0xffffffffu, s, o);
    if ((t & 31) == 0) red[t >> 5] = s;
    __syncthreads();
    if (t < 8) {
        float w = red[t];
        #pragma unroll
        for (int o = 4; o > 0; o >>= 1) w += __shfl_down_sync(0xffu, w, o);
        if (t == 0) red[0] = w;
    }
    __syncthreads();
    float inv = rsqrtf(red[0]);
    for (int i = t; i < D_; i += 256) g_xn[(size_t)b * D_ + i] = row[i] * inv;
}

// ---------------------------------------------------------------------------
// Kernel 2: fp16 mma.sync GEMM  C[256,16384] = g_xn @ tempV^T
// CTA 128x128, BK=32, 8 warps (warp tile 64x32), cp.async fp32 double buffer.
// Fragments: LDS.64 float2 -> cvt.rn.f16x2 -> mma.m16n8k16.f16 (f32 accum).
// SMEM row stride = 40 floats -> float2 fragment loads conflict-free.
// ---------------------------------------------------------------------------
#define BM 128
#define BN 128
#define BK 32
#define NCH (D_ / BK)            // 64
#define ROWSTR 40                // floats per SMEM row (32 data + 8 pad)
#define ATILE_F (BM * ROWSTR)    // 5120 floats = 20480 B
#define STAGE_F (2 * ATILE_F)    // A + B per stage (10240 floats)
#define GEMM_SMEM (2 * STAGE_F * 4)  // 81920 B

__global__ void __launch_bounds__(256, 2) kgemm(const float* __restrict__ Bmat) {
    extern __shared__ float sm[];
    uint32_t sbase = smem_u32(sm);
    int t = threadIdx.x, lane = t & 31, wid = t >> 5;
    int warp_m = (wid & 1) * 64, warp_n = (wid >> 1) * 32;
    int gid = lane >> 2, tig = lane & 3;
    int mBase = blockIdx.y * BM, nBase = blockIdx.x * BN;

    float acc[4][4][4];
    #pragma unroll
    for (int i = 0; i < 4; i++)
        #pragma unroll
        for (int j = 0; j < 4; j++)
            #pragma unroll
            for (int q = 0; q < 4; q++) acc[i][j][q] = 0.f;

    auto loadc = [&](int stage, int c) {
        int k0 = c * BK;
        uint32_t As = sbase + stage * (STAGE_F * 4);
        uint32_t Bs = As + ATILE_F * 4;
        #pragma unroll
        for (int r = 0; r < 4; r++) {
            int i = t + r * 256, row = i >> 3, q = i & 7;
            cpa16(As + (uint32_t)(row * ROWSTR + q * 4) * 4,
                  g_xn + (size_t)(mBase + row) * D_ + k0 + q * 4);
        }
        #pragma unroll
        for (int r = 0; r < 4; r++) {
            int i = t + r * 256, row = i >> 3, q = i & 7;
            cpa16(Bs + (uint32_t)(row * ROWSTR + q * 4) * 4,
                  Bmat + (size_t)(nBase + row) * D_ + k0 + q * 4);
        }
    };

    loadc(0, 0); asm volatile("cp.async.commit_group;" ::: "memory");
    loadc(1, 1); asm volatile("cp.async.commit_group;" ::: "memory");

    for (int c = 0; c < NCH; c++) {
        asm volatile("cp.async.wait_group 1;" ::: "memory");
        __syncthreads();
        const float* As = sm + (c & 1) * STAGE_F;
        const float* Bs = As + ATILE_F;
        #pragma unroll
        for (int kk = 0; kk < 2; kk++) {          // two k16 steps cover BK=32
            uint32_t a[4][4], b[4][2];
            #pragma unroll
            for (int mt = 0; mt < 4; mt++) {
                const float* p = As + (warp_m + mt * 16 + gid) * ROWSTR
                               + kk * 16 + 2 * tig;
                a[mt][0] = packh(*(const float2*)(p));
                a[mt][1] = packh(*(const float2*)(p + 8 * ROWSTR));
                a[mt][2] = packh(*(const float2*)(p + 8));
                a[mt][3] = packh(*(const float2*)(p + 8 * ROWSTR + 8));
            }
            #pragma unroll
            for (int nt = 0; nt < 4; nt++) {
                const float* p = Bs + (warp_n + nt * 8 + gid) * ROWSTR
                               + kk * 16 + 2 * tig;
                b[nt][0] = packh(*(const float2*)(p));
                b[nt][1] = packh(*(const float2*)(p + 8));
            }
            #pragma unroll
            for (int mt = 0; mt < 4; mt++)
                #pragma unroll
                for (int nt = 0; nt < 4; nt++)
                    asm volatile(
                        "mma.sync.aligned.m16n8k16.row.col.f32.f16.f16.f32 "
                        "{%0,%1,%2,%3},{%4,%5,%6,%7},{%8,%9},{%0,%1,%2,%3};"
                        : "+f"(acc[mt][nt][0]), "+f"(acc[mt][nt][1]),
                          "+f"(acc[mt][nt][2]), "+f"(acc[mt][nt][3])
                        : "r"(a[mt][0]), "r"(a[mt][1]), "r"(a[mt][2]), "r"(a[mt][3]),
                          "r"(b[nt][0]), "r"(b[nt][1]));
        }
        __syncthreads();
        if (c + 2 < NCH) loadc(c & 1, c + 2);
        asm volatile("cp.async.commit_group;" ::: "memory");
    }

    // epilogue: direct fp32 stores (float2 per c-pair)
    #pragma unroll
    for (int mt = 0; mt < 4; mt++) {
        int row0 = mBase + warp_m + mt * 16 + gid;
        #pragma unroll
        for (int nt = 0; nt < 4; nt++) {
            int col = nBase + warp_n + nt * 8 + 2 * tig;
            *(float2*)(g_logits + (size_t)row0 * NM + col) =
                make_float2(acc[mt][nt][0], acc[mt][nt][1]);
            *(float2*)(g_logits + (size_t)(row0 + 8) * NM + col) =
                make_float2(acc[mt][nt][2], acc[mt][nt][3]);
        }
    }
}

// ---------------------------------------------------------------------------
// Kernel 3: per-sample reductions, incremental top-K
// ---------------------------------------------------------------------------
__device__ __forceinline__ float blockMaxF(float v, float* scratch) {
    int t = threadIdx.x;
    #pragma unroll
    for (int o = 16; o > 0; o >>= 1) v = fmaxf(v, __shfl_down_sync(0xffffffffu, v, o));
    if ((t & 31) == 0) scratch[t >> 5] = v;
    __syncthreads();
    if (t < 8) {
        float w = scratch[t];
        #pragma unroll
        for (int o = 4; o > 0; o >>= 1) w = fmaxf(w, __shfl_down_sync(0xffu, w, o));
        if (t == 0) scratch[0] = w;
    }
    __syncthreads();
    float r = scratch[0];
    __syncthreads();
    return r;
}
__device__ __forceinline__ float blockSumF(float v, float* scratch) {
    int t = threadIdx.x;
    #pragma unroll
    for (int o = 16; o > 0; o >>= 1) v += __shfl_down_sync(0xffffffffu, v, o);
    if ((t & 31) == 0) scratch[t >> 5] = v;
    __syncthreads();
    if (t < 8) {
        float w = scratch[t];
        #pragma unroll
        for (int o = 4; o > 0; o >>= 1) w += __shfl_down_sync(0xffu, w, o);
        if (t == 0) scratch[0] = w;
    }
    __syncthreads();
    float r = scratch[0];
    __syncthreads();
    return r;
}
__device__ __forceinline__ unsigned long long packVI(float f, int idx) {
    unsigned u = __float_as_uint(f);
    u = (u & 0x80000000u) ? ~u : (u | 0x80000000u);     // order-preserving
    return ((unsigned long long)u << 32) | (unsigned)idx;
}

__global__ void __launch_bounds__(256) krow(const int* __restrict__ labels,
                                            const int* __restrict__ cams) {
    extern __shared__ float sv[];                 // NM floats (64 KB)
    __shared__ unsigned long long arr[256];
    __shared__ float fred[8];
    __shared__ unsigned long long wred[8];
    __shared__ unsigned long long s_win;
    __shared__ float s_ori[CCAM];

    int b = blockIdx.x;
    int t = threadIdx.x;
    const float* row = g_logits + (size_t)b * NM;
    for (int i = t; i < NM; i += 256) sv[i] = row[i];
    __syncthreads();

    int cam = cams[b];
    int lab = labels[b];

    // ---- intra-camera CE (unmasked values) ----
    int base = cam * P_;
    float mx = -INFINITY;
    for (int i = t; i < P_; i += 256) mx = fmaxf(mx, sv[base + i]);
    float mxall = blockMaxF(mx, fred);
    float s = 0.f;
    for (int i = t; i < P_; i += 256) s += expf((sv[base + i] - mxall) * TINV);
    float sall = blockSumF(s, fred);
    if (t == 0) {
        float lse = mxall * TINV + logf(sall);
        g_ce[b] = lse - sv[base + lab] * TINV;
    }
    __syncthreads();

    // ---- inter-camera: capture positives, then mask them ----
    float maxori = -INFINITY;
    if (t == 0) {
        #pragma unroll
        for (int c = 0; c < CCAM; c++) {
            s_ori[c] = sv[lab + P_ * c];
            maxori = fmaxf(maxori, s_ori[c]);
        }
        #pragma unroll
        for (int c = 0; c < CCAM; c++) sv[lab + P_ * c] = -10000.0f;
    }
    __syncthreads();

    // ---- initial per-thread max over strided slice ----
    unsigned long long best = 0ull;
    #pragma unroll 8
    for (int j = 0; j < NM / 256; j++) {
        int i = t + 256 * j;
        unsigned long long p = packVI(sv[i], i);
        if (p > best) best = p;
    }
    arr[t] = best;
    __syncthreads();

    // ---- 50 incremental argmax passes ----
    float m = 0.f, ssum = 0.f;    // thread 0 state
    for (int it = 0; it < KTOP; ++it) {
        unsigned long long v = arr[t];
        #pragma unroll
        for (int o = 16; o > 0; o >>= 1) {
            unsigned long long q = __shfl_down_sync(0xffffffffu, v, o);
            if (q > v) v = q;
        }
        if ((t & 31) == 0) wred[t >> 5] = v;
        __syncthreads();
        if (t < 8) {
            unsigned long long w = wred[t];
            #pragma unroll
            for (int o = 4; o > 0; o >>= 1) {
                unsigned long long q = __shfl_down_sync(0xffu, w, o);
                if (q > w) w = q;
            }
            if (t == 0) s_win = w;
        }
        __syncthreads();
        unsigned long long win = s_win;
        int idx = (int)(win & 0xffffffffu);
        if (t == 0) {
            unsigned u = (unsigned)(win >> 32);
            float val = (u & 0x80000000u) ? __uint_as_float(u ^ 0x80000000u)
                                          : __uint_as_float(~u);
            if (it == 0) {
                m = fmaxf(val, maxori);
                ssum = 0.f;
                #pragma unroll
                for (int c = 0; c < CCAM; c++) ssum += expf((s_ori[c] - m) * TINV);
            }
            ssum += expf((val - m) * TINV);
        }
        if (t == (idx & 255)) {           // owner rescans its 64-elem slice
            sv[idx] = -INFINITY;
            unsigned long long nb = 0ull;
            #pragma unroll 8
            for (int j = 0; j < NM / 256; j++) {
                int i = t + 256 * j;
                unsigned long long p = packVI(sv[i], i);
                if (p > nb) nb = p;
            }
            arr[t] = nb;
        }
        __syncthreads();
    }
    if (t == 0) {
        float lse = m * TINV + logf(ssum);
        float mean = 0.f;
        #pragma unroll
        for (int c = 0; c < CCAM; c++) mean += s_ori[c];
        mean = mean * TINV / (float)CCAM;
        g_lossk[b] = lse - mean;
    }
}

// ---------------------------------------------------------------------------
// Kernel 4: deterministic per-camera segment means -> 2 scalars
// ---------------------------------------------------------------------------
__global__ void __launch_bounds__(256) kfinal(const int* __restrict__ cams,
                                              float* __restrict__ out) {
    __shared__ int sc_cam[B_];
    __shared__ float sce[B_], slk[B_];
    __shared__ float mce[CCAM], mlk[CCAM];
    int t = threadIdx.x;
    sc_cam[t] = cams[t];
    sce[t] = g_ce[t];
    slk[t] = g_lossk[t];
    __syncthreads();
    if (t < CCAM) {
        float sc = 0.f, sl = 0.f; int cnt = 0;
        for (int i = 0; i < B_; i++) {
            if (sc_cam[i] == t) { sc += sce[i]; sl += slk[i]; cnt++; }
        }
        mce[t] = (cnt > 0) ? sc / (float)cnt : 0.f;
        mlk[t] = (cnt > 0) ? sl / (float)cnt : 0.f;
    }
    __syncthreads();
    if (t == 0) {
        float li = 0.f, lk = 0.f;
        #pragma unroll
        for (int c = 0; c < CCAM; c++) { li += mce[c]; lk += mlk[c]; }
        out[0] = li;
        out[1] = 0.5f * lk;   // LOSS_WEIGHT
    }
}

// ---------------------------------------------------------------------------
extern "C" void kernel_launch(void* const* d_in, const int* in_sizes, int n_in,
                              void* d_out, int out_size) {
    const float* x      = (const float*)d_in[0];
    const int*   labels = (const int*)d_in[1];
    const int*   cams   = (const int*)d_in[2];
    const float* tempV  = (const float*)d_in[3];
    float* out = (float*)d_out;

    knorm<<<B_, 256>>>(x);

    cudaFuncSetAttribute(kgemm, cudaFuncAttributeMaxDynamicSharedMemorySize,
                         GEMM_SMEM);
    dim3 g(NM / BN, B_ / BM);          // 128 x 2 = 256 CTAs
    kgemm<<<g, 256, GEMM_SMEM>>>(tempV);

    cudaFuncSetAttribute(krow, cudaFuncAttributeMaxDynamicSharedMemorySize,
                         NM * (int)sizeof(float) + 1024);
    krow<<<B_, 256, NM * sizeof(float)>>>(labels, cams);

    kfinal<<<1, 256>>>(cams, out);
}